// round 14
// baseline (speedup 1.0000x reference)
#include <cuda_runtime.h>

#define TT    2048
#define BB    32
#define NCTA  128
#define NTHR  256
#define ROWSZ (BB*512)        // 16384 floats per timestep of h
#define WSLICE 16384          // floats per (layer, cta) weight slice

// smem layout (floats)
#define ZX_OFF   0            // z_x : [32][512]
#define ZHA_OFF  16384        // z_hA: [32][512]
#define ZHB_OFF  32768        // z_hB: [32][512]
#define G_OFF    49152        // gates: 32*17
#define SMEM_FLOATS (G_OFF + 32*17)   // ~194 KB

__device__ __align__(256) float g_hA[(TT+1)*ROWSZ];
__device__ __align__(256) float g_hB[(TT+1)*ROWSZ];
__device__ __align__(256) float g_Wt[2*NCTA*WSLICE];   // 16 MB transposed weights
__device__ unsigned int g_count = 0;
__device__ unsigned int g_gen   = 0;

// JAX silently downcasts int64->int32 unless x64 mode is on; detect at runtime.
__device__ __forceinline__ int load_length(const void* lp, int b) {
    const int* L = (const int*)lp;
    bool is64 = true;
    #pragma unroll
    for (int w = 1; w < 32; w += 2) is64 &= (L[w] == 0);
    return is64 ? (int)((const long long*)lp)[b] : L[b];
}

__device__ __forceinline__ void cpa16(unsigned int dst, const void* src) {
    asm volatile("cp.async.cg.shared.global [%0], [%1], 16;" :: "r"(dst), "l"(src));
}
#define CPA_COMMIT() asm volatile("cp.async.commit_group;")
#define CPA_WAIT(n)  asm volatile("cp.async.wait_group %0;" :: "n"(n))

__device__ __forceinline__ unsigned int smem_u32(const void* p) {
    unsigned int a;
    asm("{ .reg .u64 t; cvta.to.shared.u64 t, %1; cvt.u32.u64 %0, t; }" : "=r"(a) : "l"(p));
    return a;
}

// hardware tanh (sm_75+): 1 MUFU op, max abs err ~1e-4
__device__ __forceinline__ float tanhapx(float x) {
    float y;
    asm("tanh.approx.f32 %0, %1;" : "=f"(y) : "f"(x));
    return y;
}

// Split grid barrier (single-counter, proven in R11/R12).
__device__ __forceinline__ void grid_arrive() {
    __threadfence();
    __syncthreads();
    if (threadIdx.x == 0) {
        if (atomicAdd(&g_count, 1u) == NCTA - 1u) {
            atomicExch(&g_count, 0u);
            __threadfence();
            atomicAdd(&g_gen, 1u);
        }
    }
}
__device__ __forceinline__ void grid_wait(unsigned int target) {
    if (threadIdx.x == 0) {
        volatile unsigned int* vg = &g_gen;
        while ((int)(*vg - target) < 0) {}
    }
    __syncthreads();
}

// 64-iter GEMM segment: W streamed from gmem (L2-hot), z from smem.
__device__ __forceinline__ void gemm_seg64(const float* __restrict__ wp,
                                           const float* zp,
                                           float& a0, float& a1, float& a2, float& a3) {
    #pragma unroll 8
    for (int j = 0; j < 64; ++j) {
        float4 w  = *(const float4*)(wp + (j << 6));
        float4 z0 = *(const float4*)(zp + (j << 2));
        float4 z1 = *(const float4*)(zp + 512  + (j << 2));
        float4 z2 = *(const float4*)(zp + 1024 + (j << 2));
        float4 z3 = *(const float4*)(zp + 1536 + (j << 2));
        a0 += z0.x*w.x; a0 += z0.y*w.y; a0 += z0.z*w.z; a0 += z0.w*w.w;
        a1 += z1.x*w.x; a1 += z1.y*w.y; a1 += z1.z*w.z; a1 += z1.w*w.w;
        a2 += z2.x*w.x; a2 += z2.y*w.y; a2 += z2.z*w.z; a2 += z2.w*w.w;
        a3 += z3.x*w.x; a3 += z3.y*w.y; a3 += z3.z*w.z; a3 += z3.w*w.w;
    }
}
__device__ __forceinline__ void gemm_seg32(const float* __restrict__ wp,
                                           const float* zp,
                                           float& a0, float& a1, float& a2, float& a3) {
    #pragma unroll 8
    for (int j = 0; j < 32; ++j) {
        float4 w  = *(const float4*)(wp + (j << 6));
        float4 z0 = *(const float4*)(zp + (j << 2));
        float4 z1 = *(const float4*)(zp + 512  + (j << 2));
        float4 z2 = *(const float4*)(zp + 1024 + (j << 2));
        float4 z3 = *(const float4*)(zp + 1536 + (j << 2));
        a0 += z0.x*w.x; a0 += z0.y*w.y; a0 += z0.z*w.z; a0 += z0.w*w.w;
        a1 += z1.x*w.x; a1 += z1.y*w.y; a1 += z1.z*w.z; a1 += z1.w*w.w;
        a2 += z2.x*w.x; a2 += z2.y*w.y; a2 += z2.z*w.z; a2 += z2.w*w.w;
        a3 += z3.x*w.x; a3 += z3.y*w.y; a3 += z3.z*w.z; a3 += z3.w*w.w;
    }
}

__global__ void __launch_bounds__(NTHR, 1)
lstm_persistent(const float* __restrict__ x,
                const void* __restrict__ length,
                const float* __restrict__ Wih0, const float* __restrict__ Whh0,
                const float* __restrict__ b0v,
                const float* __restrict__ Wih1, const float* __restrict__ Whh1,
                const float* __restrict__ b1v)
{
    extern __shared__ float smem[];
    float* z_x     = smem + ZX_OFF;
    float* z_hA    = smem + ZHA_OFF;
    float* z_hB    = smem + ZHB_OFF;
    float* gates_s = smem + G_OFF;
    const unsigned int zx_u  = smem_u32(z_x);
    const unsigned int zhA_u = smem_u32(z_hA);
    const unsigned int zhB_u = smem_u32(z_hB);

    const int tid   = threadIdx.x;
    const int hbase = blockIdx.x * 4;

    const unsigned int bar_base = *((volatile unsigned int*)&g_gen);

    const int c   = tid & 15;              // gate column (c = hh*4 + gate)
    const int bh  = (tid >> 4) & 1;
    const int bg  = (tid >> 5) & 3;
    const int kh  = tid >> 7;              // K-half
    const int b0i = bg*8 + bh*4;           // 4 batch rows per thread

    const int eb  = tid & 31;              // elementwise mapping (tid<128)
    const int ehh = tid >> 5;
    int lb = 0;
    if (tid < 128) lb = load_length(length, eb);

    // ---- pre-phase: build per-CTA transposed W slices (own slice only) ----
    for (int layer = 0; layer < 2; ++layer) {
        const float* Wih = layer ? Wih1 : Wih0;
        const float* Whh = layer ? Whh1 : Whh0;
        float* dst = g_Wt + (size_t)(layer*NCTA + blockIdx.x)*WSLICE;
        for (int i = tid; i < 16384; i += NTHR) {
            int k  = i >> 4;
            int cc = i & 15;
            int col = ((cc & 3) << 9) + hbase + (cc >> 2);
            float w = (k < 512) ? Wih[(size_t)k*2048 + col]
                                : Whh[(size_t)(k-512)*2048 + col];
            dst[((k >> 2) << 6) + (cc << 2) + (k & 3)] = w;
        }
    }
    __threadfence();
    __syncthreads();

    const float* W0 = g_Wt + (size_t)blockIdx.x*WSLICE;
    const float* W1 = g_Wt + (size_t)(NCTA + blockIdx.x)*WSLICE;
    const float bv0 = b0v[((c & 3) << 9) + hbase + (c >> 2)];
    const float bv1 = b1v[((c & 3) << 9) + hbase + (c >> 2)];

    // prime x(0) into registers
    float4 xp[16];
    {
        const float4* xr = (const float4*)x;
        #pragma unroll
        for (int j = 0; j < 16; ++j) xp[j] = __ldcg(xr + tid + j*NTHR);
    }

    float c0reg = 0.f, h0reg = 0.f;   // layer-0 state (tid<128: (eb, ehh))
    float c1reg = 0.f, h1reg = 0.f;   // layer-1 state

    for (int s = 0; s <= TT; ++s) {
        const bool doL0 = (s < TT);
        const bool doL1 = (s >= 1);

        // 1) store x(s) regs -> z_x, then prefetch x(s+1)
        if (doL0) {
            #pragma unroll
            for (int j = 0; j < 16; ++j) {
                int i = tid + j*NTHR;
                int b = i >> 7, k4 = i & 127;
                *(float4*)(z_x + (b << 9) + (k4 << 2)) = xp[j];
            }
        }
        __syncthreads();
        if (doL0) {
            int tn = (s + 1 < TT) ? (s + 1) : (TT - 1);
            const float4* xnext = (const float4*)(x + (size_t)tn*ROWSZ);
            #pragma unroll
            for (int j = 0; j < 16; ++j) xp[j] = __ldcg(xnext + tid + j*NTHR);
        }

        float a0 = 0.f, a1 = 0.f, a2 = 0.f, a3 = 0.f;
        const float* wx0 = W0 + (kh*64)*64 + (c << 2);       // x-part k4 base
        const float* zxp = z_x + b0i*512 + kh*256;

        // 2) L0 x-GEMM half A — slack absorbing barrier skew
        if (doL0) gemm_seg32(wx0, zxp, a0, a1, a2, a3);

        // 3) wait superstep s-1 complete (usually already satisfied)
        grid_wait(bar_base + (unsigned)s);

        // 4) stage hA(s) and hB(s-1) async (two groups)
        {
            const float* hrow = g_hA + (size_t)s*ROWSZ;
            #pragma unroll
            for (int j = 0; j < 16; ++j) {
                int i = tid + j*NTHR;
                int b = i >> 7, k4 = i & 127;
                cpa16(zhA_u + ((b << 9) + (k4 << 2))*4, hrow + b*512 + (k4 << 2));
            }
            CPA_COMMIT();
            const float* hrowB = g_hB + (size_t)(doL1 ? s-1 : 0)*ROWSZ;
            #pragma unroll
            for (int j = 0; j < 16; ++j) {
                int i = tid + j*NTHR;
                int b = i >> 7, k4 = i & 127;
                cpa16(zhB_u + ((b << 9) + (k4 << 2))*4, hrowB + b*512 + (k4 << 2));
            }
            CPA_COMMIT();
        }

        // 5) L0 x-GEMM half B — hides hA transfer
        if (doL0) gemm_seg32(wx0 + 32*64, zxp + 128, a0, a1, a2, a3);

        // 6) hA resident
        CPA_WAIT(1);
        __syncthreads();

        // 7) L0 h-GEMM + reduce + elementwise + store hA(s+1)
        if (doL0) {
            gemm_seg64(W0 + (128 + kh*64)*64 + (c << 2),
                       z_hA + b0i*512 + kh*256, a0, a1, a2, a3);
            if (kh == 1) {
                gates_s[(b0i+0)*17 + c] = a0;
                gates_s[(b0i+1)*17 + c] = a1;
                gates_s[(b0i+2)*17 + c] = a2;
                gates_s[(b0i+3)*17 + c] = a3;
            }
            __syncthreads();
            if (kh == 0) {
                gates_s[(b0i+0)*17 + c] += a0 + bv0;
                gates_s[(b0i+1)*17 + c] += a1 + bv0;
                gates_s[(b0i+2)*17 + c] += a2 + bv0;
                gates_s[(b0i+3)*17 + c] += a3 + bv0;
            }
            __syncthreads();
            if (tid < 128) {
                float fg = gates_s[eb*17 + ehh*4 + 0];
                float ig = gates_s[eb*17 + ehh*4 + 1];
                float og = gates_s[eb*17 + ehh*4 + 2];
                float gg = gates_s[eb*17 + ehh*4 + 3];
                float cn, hn;
                if (s < lb) {
                    float sf = 0.5f*tanhapx(0.5f*fg) + 0.5f;
                    float si = 0.5f*tanhapx(0.5f*ig) + 0.5f;
                    float so = 0.5f*tanhapx(0.5f*og) + 0.5f;
                    cn = sf*c0reg + si*tanhapx(gg);
                    hn = so*tanhapx(cn);
                } else { cn = c0reg; hn = h0reg; }
                c0reg = cn; h0reg = hn;
                g_hA[(size_t)(s+1)*ROWSZ + eb*512 + hbase + ehh] = hn;
            }
        }

        // 8) hB resident
        CPA_WAIT(0);
        __syncthreads();

        // 9) L1 full GEMM (x-part = hA(s), h-part = hB(s-1)) + finish
        if (doL1) {
            float d0 = 0.f, d1 = 0.f, d2 = 0.f, d3 = 0.f;
            gemm_seg64(W1 + (kh*64)*64 + (c << 2),
                       z_hA + b0i*512 + kh*256, d0, d1, d2, d3);
            gemm_seg64(W1 + (128 + kh*64)*64 + (c << 2),
                       z_hB + b0i*512 + kh*256, d0, d1, d2, d3);
            if (kh == 1) {
                gates_s[(b0i+0)*17 + c] = d0;
                gates_s[(b0i+1)*17 + c] = d1;
                gates_s[(b0i+2)*17 + c] = d2;
                gates_s[(b0i+3)*17 + c] = d3;
            }
            __syncthreads();
            if (kh == 0) {
                gates_s[(b0i+0)*17 + c] += d0 + bv1;
                gates_s[(b0i+1)*17 + c] += d1 + bv1;
                gates_s[(b0i+2)*17 + c] += d2 + bv1;
                gates_s[(b0i+3)*17 + c] += d3 + bv1;
            }
            __syncthreads();
            if (tid < 128) {
                float fg = gates_s[eb*17 + ehh*4 + 0];
                float ig = gates_s[eb*17 + ehh*4 + 1];
                float og = gates_s[eb*17 + ehh*4 + 2];
                float gg = gates_s[eb*17 + ehh*4 + 3];
                float cn, hn;
                if ((s - 1) < lb) {
                    float sf = 0.5f*tanhapx(0.5f*fg) + 0.5f;
                    float si = 0.5f*tanhapx(0.5f*ig) + 0.5f;
                    float so = 0.5f*tanhapx(0.5f*og) + 0.5f;
                    cn = sf*c1reg + si*tanhapx(gg);
                    hn = so*tanhapx(cn);
                } else { cn = c1reg; hn = h1reg; }
                c1reg = cn; h1reg = hn;
                g_hB[(size_t)s*ROWSZ + eb*512 + hbase + ehh] = hn;
            }
        }

        // 10) arrive (end of superstep s -> gen = bar_base + s + 1)
        grid_arrive();
    }
}

// out[r][a] = h1[r] . Wfc[:,a] + bfc[a],  h1 row = g_hB row r+32
__global__ void __launch_bounds__(256)
fc_kernel(const float* __restrict__ Wfc, const float* __restrict__ bfc,
          float* __restrict__ out)
{
    __shared__ float w_s[128*64];
    __shared__ float h_s[32*128];
    const int tid = threadIdx.x;
    const int rbase = blockIdx.x * 32;
    const int a  = tid & 63;
    const int r4 = tid >> 6;

    float acc[8];
    float bvv = bfc[a];
    #pragma unroll
    for (int j = 0; j < 8; ++j) acc[j] = bvv;

    for (int kc = 0; kc < 512; kc += 128) {
        __syncthreads();
        for (int i = tid; i < 128*64/4; i += 256)
            ((float4*)w_s)[i] = ((const float4*)(Wfc + (size_t)kc*64))[i];
        for (int i = tid; i < 32*128/4; i += 256) {
            int r  = i >> 5;
            int k4 = i & 31;
            ((float4*)(h_s + r*128))[k4] =
                *(const float4*)(g_hB + (size_t)(rbase + r + BB)*512 + kc + (k4 << 2));
        }
        __syncthreads();
        #pragma unroll 4
        for (int k = 0; k < 128; ++k) {
            float w = w_s[(k << 6) + a];
            #pragma unroll
            for (int j = 0; j < 8; ++j)
                acc[j] += h_s[(r4 + 4*j)*128 + k] * w;
        }
    }
    #pragma unroll
    for (int j = 0; j < 8; ++j)
        out[(size_t)(rbase + r4 + 4*j)*64 + a] = acc[j];
}

extern "C" void kernel_launch(void* const* d_in, const int* in_sizes, int n_in,
                              void* d_out, int out_size)
{
    const float* x      = (const float*)d_in[0];
    const void*  length = (const void*)d_in[1];
    const float* Wih0   = (const float*)d_in[2];
    const float* Whh0   = (const float*)d_in[3];
    const float* b0v    = (const float*)d_in[4];
    const float* Wih1   = (const float*)d_in[5];
    const float* Whh1   = (const float*)d_in[6];
    const float* b1v    = (const float*)d_in[7];
    const float* Wfc    = (const float*)d_in[8];
    const float* bfc    = (const float*)d_in[9];
    float* out = (float*)d_out;

    const int smem_bytes = SMEM_FLOATS * (int)sizeof(float); // ~194 KB
    cudaFuncSetAttribute(lstm_persistent,
                         cudaFuncAttributeMaxDynamicSharedMemorySize, smem_bytes);

    lstm_persistent<<<NCTA, NTHR, smem_bytes>>>(x, length, Wih0, Whh0, b0v,
                                                Wih1, Whh1, b1v);
    fc_kernel<<<(TT*BB)/32, 256>>>(Wfc, bfc, out);
}

// round 15
// speedup vs baseline: 1.1330x; 1.1330x over previous
#include <cuda_runtime.h>

#define TT    2048
#define BB    32
#define NCTA  128
#define NTHR  256
#define ROWSZ (BB*512)        // 16384 floats per timestep of h

// smem layout (floats)
#define BUF0_OFF 0            // role-swapping z buffer 0: [32][512]
#define BUF1_OFF 16384        // role-swapping z buffer 1: [32][512]
#define W0_OFF   32768        // W0 resident: 16384
#define WBA_OFF  49152        // W1 stream buf A: 4096
#define WBB_OFF  53248        // W1 stream buf B: 4096
#define G_OFF    57344        // gates: 32*17
#define SMEM_FLOATS (G_OFF + 32*17)   // 57888 floats = 226.1 KB

__device__ __align__(256) float g_hA[(TT+1)*ROWSZ];
__device__ __align__(256) float g_hB[(TT+1)*ROWSZ];
__device__ __align__(256) float g_W1t[NCTA*16384];    // 8 MB phase-major W1
__device__ unsigned int g_count = 0;
__device__ unsigned int g_gen   = 0;

// JAX silently downcasts int64->int32 unless x64 mode is on; detect at runtime.
__device__ __forceinline__ int load_length(const void* lp, int b) {
    const int* L = (const int*)lp;
    bool is64 = true;
    #pragma unroll
    for (int w = 1; w < 32; w += 2) is64 &= (L[w] == 0);
    return is64 ? (int)((const long long*)lp)[b] : L[b];
}

__device__ __forceinline__ void cpa16(unsigned int dst, const void* src) {
    asm volatile("cp.async.cg.shared.global [%0], [%1], 16;" :: "r"(dst), "l"(src));
}
#define CPA_COMMIT() asm volatile("cp.async.commit_group;")
#define CPA_WAIT0()  asm volatile("cp.async.wait_group 0;")

__device__ __forceinline__ unsigned int smem_u32(const void* p) {
    unsigned int a;
    asm("{ .reg .u64 t; cvta.to.shared.u64 t, %1; cvt.u32.u64 %0, t; }" : "=r"(a) : "l"(p));
    return a;
}

// hardware tanh (sm_75+): 1 MUFU op, max abs err ~1e-4
__device__ __forceinline__ float tanhapx(float x) {
    float y;
    asm("tanh.approx.f32 %0, %1;" : "=f"(y) : "f"(x));
    return y;
}

// Split grid barrier (single-counter, R11/R12-proven).
__device__ __forceinline__ void grid_arrive() {
    __threadfence();
    __syncthreads();
    if (threadIdx.x == 0) {
        if (atomicAdd(&g_count, 1u) == NCTA - 1u) {
            atomicExch(&g_count, 0u);
            __threadfence();
            atomicAdd(&g_gen, 1u);
        }
    }
}
__device__ __forceinline__ void grid_wait(unsigned int target) {
    if (threadIdx.x == 0) {
        volatile unsigned int* vg = &g_gen;
        while ((int)(*vg - target) < 0) {}
    }
    __syncthreads();
}

// GEMM segments: W + z from smem only (proven inner loop).
__device__ __forceinline__ void gemm_seg32(const float* wp, const float* zp,
                                           float& a0, float& a1, float& a2, float& a3) {
    #pragma unroll 8
    for (int j = 0; j < 32; ++j) {
        float4 w  = *(const float4*)(wp + (j << 6));
        float4 z0 = *(const float4*)(zp + (j << 2));
        float4 z1 = *(const float4*)(zp + 512  + (j << 2));
        float4 z2 = *(const float4*)(zp + 1024 + (j << 2));
        float4 z3 = *(const float4*)(zp + 1536 + (j << 2));
        a0 += z0.x*w.x; a0 += z0.y*w.y; a0 += z0.z*w.z; a0 += z0.w*w.w;
        a1 += z1.x*w.x; a1 += z1.y*w.y; a1 += z1.z*w.z; a1 += z1.w*w.w;
        a2 += z2.x*w.x; a2 += z2.y*w.y; a2 += z2.z*w.z; a2 += z2.w*w.w;
        a3 += z3.x*w.x; a3 += z3.y*w.y; a3 += z3.z*w.z; a3 += z3.w*w.w;
    }
}
__device__ __forceinline__ void gemm_seg64(const float* wp, const float* zp,
                                           float& a0, float& a1, float& a2, float& a3) {
    #pragma unroll 8
    for (int j = 0; j < 64; ++j) {
        float4 w  = *(const float4*)(wp + (j << 6));
        float4 z0 = *(const float4*)(zp + (j << 2));
        float4 z1 = *(const float4*)(zp + 512  + (j << 2));
        float4 z2 = *(const float4*)(zp + 1024 + (j << 2));
        float4 z3 = *(const float4*)(zp + 1536 + (j << 2));
        a0 += z0.x*w.x; a0 += z0.y*w.y; a0 += z0.z*w.z; a0 += z0.w*w.w;
        a1 += z1.x*w.x; a1 += z1.y*w.y; a1 += z1.z*w.z; a1 += z1.w*w.w;
        a2 += z2.x*w.x; a2 += z2.y*w.y; a2 += z2.z*w.z; a2 += z2.w*w.w;
        a3 += z3.x*w.x; a3 += z3.y*w.y; a3 += z3.z*w.z; a3 += z3.w*w.w;
    }
}

__global__ void __launch_bounds__(NTHR, 1)
lstm_persistent(const float* __restrict__ x,
                const void* __restrict__ length,
                const float* __restrict__ Wih0, const float* __restrict__ Whh0,
                const float* __restrict__ b0v,
                const float* __restrict__ Wih1, const float* __restrict__ Whh1,
                const float* __restrict__ b1v)
{
    extern __shared__ float smem[];
    float* buf0    = smem + BUF0_OFF;
    float* buf1    = smem + BUF1_OFF;
    float* W0_s    = smem + W0_OFF;
    float* wbufA   = smem + WBA_OFF;
    float* wbufB   = smem + WBB_OFF;
    float* gates_s = smem + G_OFF;
    const unsigned int b0_u = smem_u32(buf0);
    const unsigned int b1_u = smem_u32(buf1);
    const unsigned int wA_u = smem_u32(wbufA);
    const unsigned int wB_u = smem_u32(wbufB);

    const int tid   = threadIdx.x;
    const int hbase = blockIdx.x * 4;

    const unsigned int bar_base = *((volatile unsigned int*)&g_gen);

    const int c   = tid & 15;              // gate column (c = hh*4 + gate)
    const int bh_ = (tid >> 4) & 1;
    const int bg  = (tid >> 5) & 3;
    const int kh  = tid >> 7;              // K-half
    const int b0i = bg*8 + bh_*4;          // 4 batch rows per thread

    const int eb  = tid & 31;              // elementwise mapping (tid<128)
    const int ehh = tid >> 5;
    int lb = 0;
    if (tid < 128) lb = load_length(length, eb);

    // ---- pre-phase 1: W0 resident in smem (R13 layout) ----
    for (int i = tid; i < 16384; i += NTHR) {
        int k  = i >> 4;
        int cc = i & 15;
        int col = ((cc & 3) << 9) + hbase + (cc >> 2);
        float w = (k < 512) ? Wih0[(size_t)k*2048 + col]
                            : Whh0[(size_t)(k-512)*2048 + col];
        W0_s[((k >> 2) << 6) + (cc << 2) + (k & 3)] = w;
    }

    // ---- pre-phase 2: W1 -> per-CTA gmem slice, phase-major layout ----
    // phase p in {xA,xB,hA,hB}; within phase: [kh][j(32)][cc2(64)]
    {
        float* dst = g_W1t + (size_t)blockIdx.x * 16384;
        for (int i = tid; i < 16384; i += NTHR) {
            int p    = i >> 12;
            int khh  = (i >> 11) & 1;
            int j    = (i >> 6) & 31;
            int cc2  = i & 63;
            int cidx = cc2 >> 2;
            int klow = cc2 & 3;
            int k4g  = ((p & 1) << 5) + (khh << 6) + (((p >> 1) & 1) << 7) + j;
            int k    = (k4g << 2) + klow;
            int col  = ((cidx & 3) << 9) + hbase + (cidx >> 2);
            dst[i] = (k < 512) ? Wih1[(size_t)k*2048 + col]
                               : Whh1[(size_t)(k-512)*2048 + col];
        }
    }
    __threadfence();
    __syncthreads();

    const float* W1g = g_W1t + (size_t)blockIdx.x * 16384;
    const float bv0 = b0v[((c & 3) << 9) + hbase + (c >> 2)];
    const float bv1 = b1v[((c & 3) << 9) + hbase + (c >> 2)];

    // ---- prime: x(0) -> buf0, W1 phase0 -> wbufA (one group) ----
    #pragma unroll
    for (int j = 0; j < 16; ++j) {
        int i = tid + j*NTHR;
        int b = i >> 7, k4 = i & 127;
        cpa16(b0_u + ((b << 9) + (k4 << 2))*4, x + b*512 + (k4 << 2));
    }
    #pragma unroll
    for (int j = 0; j < 4; ++j) {
        int i = tid + j*NTHR;            // 0..1023 -> 4096 floats
        cpa16(wA_u + (i << 4), W1g + (i << 2));
    }
    CPA_COMMIT();

    float c0reg = 0.f, h0reg = 0.f;   // layer-0 state (tid<128)
    float c1reg = 0.f, h1reg = 0.f;   // layer-1 state

    for (int s = 0; s <= TT; ++s) {
        const bool doL0 = (s < TT);
        const bool doL1 = (s >= 1);
        float* bx = (s & 1) ? buf1 : buf0;            // holds x(s)
        float* bz = (s & 1) ? buf0 : buf1;            // gets hA(s), then x(s+1)
        const unsigned int bx_u = (s & 1) ? b1_u : b0_u;
        const unsigned int bz_u = (s & 1) ? b0_u : b1_u;

        // T0: everything from previous superstep landed (x(s), W1 phase0)
        CPA_WAIT0();
        __syncthreads();

        float a0 = 0.f, a1 = 0.f, a2 = 0.f, a3 = 0.f;
        const float* zpx = bx + b0i*512 + kh*256;

        // L0 x-GEMM phase A (k4 0-31 per kh)
        if (doL0) gemm_seg32(W0_s + kh*4096 + (c << 2), zpx, a0, a1, a2, a3);

        // wait superstep s-1 complete (h rows for s ready)
        grid_wait(bar_base + (unsigned)s);

        // G1: hA(s) -> bz
        {
            const float* hrow = g_hA + (size_t)s*ROWSZ;
            #pragma unroll
            for (int j = 0; j < 16; ++j) {
                int i = tid + j*NTHR;
                int b = i >> 7, k4 = i & 127;
                cpa16(bz_u + ((b << 9) + (k4 << 2))*4, hrow + b*512 + (k4 << 2));
            }
            CPA_COMMIT();
        }

        // L0 x-GEMM phase B — hides G1
        if (doL0) gemm_seg32(W0_s + kh*4096 + 2048 + (c << 2), zpx + 128, a0, a1, a2, a3);

        CPA_WAIT0();          // G1 done; bx(x) reads closed
        __syncthreads();

        // G2: hB(s-1) -> bx (x dead)  +  W1 phase1 -> wbufB
        {
            const float* hrowB = g_hB + (size_t)(doL1 ? s-1 : 0)*ROWSZ;
            #pragma unroll
            for (int j = 0; j < 16; ++j) {
                int i = tid + j*NTHR;
                int b = i >> 7, k4 = i & 127;
                cpa16(bx_u + ((b << 9) + (k4 << 2))*4, hrowB + b*512 + (k4 << 2));
            }
            #pragma unroll
            for (int j = 0; j < 4; ++j) {
                int i = tid + j*NTHR;
                cpa16(wB_u + (i << 4), W1g + 4096 + (i << 2));
            }
            CPA_COMMIT();
        }

        // L0 h-GEMM (k4 0-63 per kh) from bz=hA(s) — 4096 cyc, hides G2
        if (doL0) {
            gemm_seg64(W0_s + 8192 + kh*4096 + (c << 2),
                       bz + b0i*512 + kh*256, a0, a1, a2, a3);
        }

        // L0 reduce + elementwise (syncs unconditional)
        if (doL0 && kh == 1) {
            gates_s[(b0i+0)*17 + c] = a0;
            gates_s[(b0i+1)*17 + c] = a1;
            gates_s[(b0i+2)*17 + c] = a2;
            gates_s[(b0i+3)*17 + c] = a3;
        }
        __syncthreads();
        if (doL0 && kh == 0) {
            gates_s[(b0i+0)*17 + c] += a0 + bv0;
            gates_s[(b0i+1)*17 + c] += a1 + bv0;
            gates_s[(b0i+2)*17 + c] += a2 + bv0;
            gates_s[(b0i+3)*17 + c] += a3 + bv0;
        }
        __syncthreads();
        if (doL0 && tid < 128) {
            float fg = gates_s[eb*17 + ehh*4 + 0];
            float ig = gates_s[eb*17 + ehh*4 + 1];
            float og = gates_s[eb*17 + ehh*4 + 2];
            float gg = gates_s[eb*17 + ehh*4 + 3];
            float cn, hn;
            if (s < lb) {
                float sf = 0.5f*tanhapx(0.5f*fg) + 0.5f;
                float si = 0.5f*tanhapx(0.5f*ig) + 0.5f;
                float so = 0.5f*tanhapx(0.5f*og) + 0.5f;
                cn = sf*c0reg + si*tanhapx(gg);
                hn = so*tanhapx(cn);
            } else { cn = c0reg; hn = h0reg; }
            c0reg = cn; h0reg = hn;
            g_hA[(size_t)(s+1)*ROWSZ + eb*512 + hbase + ehh] = hn;
        }

        // ---- layer 1 (processes timestep s-1) ----
        float d0 = 0.f, d1 = 0.f, d2 = 0.f, d3 = 0.f;
        const float* zpa = bz + b0i*512 + kh*256;   // hA(s)
        const float* zpb = bx + b0i*512 + kh*256;   // hB(s-1)

        // L1 x-GEMM phase A from wbufA(phase0) ⊗ hA
        if (doL1) gemm_seg32(wbufA + kh*2048 + (c << 2), zpa, d0, d1, d2, d3);

        CPA_WAIT0();          // G2 done (bx=hB, wbufB=phase1)
        __syncthreads();

        // G3: W1 phase2 -> wbufA (phase0 consumed)
        #pragma unroll
        for (int j = 0; j < 4; ++j) {
            int i = tid + j*NTHR;
            cpa16(wA_u + (i << 4), W1g + 8192 + (i << 2));
        }
        CPA_COMMIT();

        // L1 x-GEMM phase B from wbufB(phase1) — hides G3
        if (doL1) gemm_seg32(wbufB + kh*2048 + (c << 2), zpa + 128, d0, d1, d2, d3);

        CPA_WAIT0();          // G3 done
        __syncthreads();

        // G4: W1 phase3 -> wbufB  +  x(s+1) -> bz (hA reads closed)
        {
            int tn = (s + 1 < TT) ? (s + 1) : (TT - 1);
            const float* xnext = x + (size_t)tn*ROWSZ;
            #pragma unroll
            for (int j = 0; j < 4; ++j) {
                int i = tid + j*NTHR;
                cpa16(wB_u + (i << 4), W1g + 12288 + (i << 2));
            }
            #pragma unroll
            for (int j = 0; j < 16; ++j) {
                int i = tid + j*NTHR;
                int b = i >> 7, k4 = i & 127;
                cpa16(bz_u + ((b << 9) + (k4 << 2))*4, xnext + b*512 + (k4 << 2));
            }
            CPA_COMMIT();
        }

        // L1 h-GEMM phase A from wbufA(phase2) ⊗ hB — hides G4
        if (doL1) gemm_seg32(wbufA + kh*2048 + (c << 2), zpb, d0, d1, d2, d3);

        CPA_WAIT0();          // G4 done
        __syncthreads();

        // G5: W1 phase0 -> wbufA for next superstep
        #pragma unroll
        for (int j = 0; j < 4; ++j) {
            int i = tid + j*NTHR;
            cpa16(wA_u + (i << 4), W1g + (i << 2));
        }
        CPA_COMMIT();

        // L1 h-GEMM phase B from wbufB(phase3) — hides G5
        if (doL1) gemm_seg32(wbufB + kh*2048 + (c << 2), zpb + 128, d0, d1, d2, d3);

        // L1 reduce + elementwise
        if (doL1 && kh == 1) {
            gates_s[(b0i+0)*17 + c] = d0;
            gates_s[(b0i+1)*17 + c] = d1;
            gates_s[(b0i+2)*17 + c] = d2;
            gates_s[(b0i+3)*17 + c] = d3;
        }
        __syncthreads();
        if (doL1 && kh == 0) {
            gates_s[(b0i+0)*17 + c] += d0 + bv1;
            gates_s[(b0i+1)*17 + c] += d1 + bv1;
            gates_s[(b0i+2)*17 + c] += d2 + bv1;
            gates_s[(b0i+3)*17 + c] += d3 + bv1;
        }
        __syncthreads();
        if (doL1 && tid < 128) {
            float fg = gates_s[eb*17 + ehh*4 + 0];
            float ig = gates_s[eb*17 + ehh*4 + 1];
            float og = gates_s[eb*17 + ehh*4 + 2];
            float gg = gates_s[eb*17 + ehh*4 + 3];
            float cn, hn;
            if ((s - 1) < lb) {
                float sf = 0.5f*tanhapx(0.5f*fg) + 0.5f;
                float si = 0.5f*tanhapx(0.5f*ig) + 0.5f;
                float so = 0.5f*tanhapx(0.5f*og) + 0.5f;
                cn = sf*c1reg + si*tanhapx(gg);
                hn = so*tanhapx(cn);
            } else { cn = c1reg; hn = h1reg; }
            c1reg = cn; h1reg = hn;
            g_hB[(size_t)s*ROWSZ + eb*512 + hbase + ehh] = hn;
        }

        grid_arrive();   // gen -> bar_base + s + 1
    }
}

// out[r][a] = h1[r] . Wfc[:,a] + bfc[a],  h1 row = g_hB row r+32
__global__ void __launch_bounds__(256)
fc_kernel(const float* __restrict__ Wfc, const float* __restrict__ bfc,
          float* __restrict__ out)
{
    __shared__ float w_s[128*64];
    __shared__ float h_s[32*128];
    const int tid = threadIdx.x;
    const int rbase = blockIdx.x * 32;
    const int a  = tid & 63;
    const int r4 = tid >> 6;

    float acc[8];
    float bvv = bfc[a];
    #pragma unroll
    for (int j = 0; j < 8; ++j) acc[j] = bvv;

    for (int kc = 0; kc < 512; kc += 128) {
        __syncthreads();
        for (int i = tid; i < 128*64/4; i += 256)
            ((float4*)w_s)[i] = ((const float4*)(Wfc + (size_t)kc*64))[i];
        for (int i = tid; i < 32*128/4; i += 256) {
            int r  = i >> 5;
            int k4 = i & 31;
            ((float4*)(h_s + r*128))[k4] =
                *(const float4*)(g_hB + (size_t)(rbase + r + BB)*512 + kc + (k4 << 2));
        }
        __syncthreads();
        #pragma unroll 4
        for (int k = 0; k < 128; ++k) {
            float w = w_s[(k << 6) + a];
            #pragma unroll
            for (int j = 0; j < 8; ++j)
                acc[j] += h_s[(r4 + 4*j)*128 + k] * w;
        }
    }
    #pragma unroll
    for (int j = 0; j < 8; ++j)
        out[(size_t)(rbase + r4 + 4*j)*64 + a] = acc[j];
}

extern "C" void kernel_launch(void* const* d_in, const int* in_sizes, int n_in,
                              void* d_out, int out_size)
{
    const float* x      = (const float*)d_in[0];
    const void*  length = (const void*)d_in[1];
    const float* Wih0   = (const float*)d_in[2];
    const float* Whh0   = (const float*)d_in[3];
    const float* b0v    = (const float*)d_in[4];
    const float* Wih1   = (const float*)d_in[5];
    const float* Whh1   = (const float*)d_in[6];
    const float* b1v    = (const float*)d_in[7];
    const float* Wfc    = (const float*)d_in[8];
    const float* bfc    = (const float*)d_in[9];
    float* out = (float*)d_out;

    const int smem_bytes = SMEM_FLOATS * (int)sizeof(float); // ~226 KB
    cudaFuncSetAttribute(lstm_persistent,
                         cudaFuncAttributeMaxDynamicSharedMemorySize, smem_bytes);

    lstm_persistent<<<NCTA, NTHR, smem_bytes>>>(x, length, Wih0, Whh0, b0v,
                                                Wih1, Whh1, b1v);
    fc_kernel<<<(TT*BB)/32, 256>>>(Wfc, bfc, out);
}

// round 16
// speedup vs baseline: 1.4498x; 1.2795x over previous
#include <cuda_runtime.h>

#define TT    2048
#define BB    32
#define NCTA  128
#define NTHR  256
#define ROWSZ (BB*512)        // 16384 floats per timestep of h

// smem layout (floats)
#define BUF0_OFF 0            // role-swapping z buffer 0: [32][512]
#define BUF1_OFF 16384        // role-swapping z buffer 1: [32][512]
#define W0_OFF   32768        // W0 resident: 16384
#define WBA_OFF  49152        // W1 stream buf A: 4096
#define WBB_OFF  53248        // W1 stream buf B: 4096
#define G_OFF    57344        // gates: 32*17
#define SRT_OFF  (G_OFF + 32*17)      // sidx[32] + lenS[32] (as int)
#define SMEM_FLOATS (SRT_OFF + 64)    // 57952 floats = 226.4 KB

__device__ __align__(256) float g_hA[(TT+1)*ROWSZ];
__device__ __align__(256) float g_hB[(TT+1)*ROWSZ];
__device__ __align__(256) float g_W1t[NCTA*16384];    // 8 MB phase-major W1
__device__ int g_sidx_d[32];
__device__ unsigned int g_count = 0;
__device__ unsigned int g_gen   = 0;

// JAX silently downcasts int64->int32 unless x64 mode is on; detect at runtime.
__device__ __forceinline__ int load_length(const void* lp, int b) {
    const int* L = (const int*)lp;
    bool is64 = true;
    #pragma unroll
    for (int w = 1; w < 32; w += 2) is64 &= (L[w] == 0);
    return is64 ? (int)((const long long*)lp)[b] : L[b];
}

__device__ __forceinline__ void cpa16(unsigned int dst, const void* src) {
    asm volatile("cp.async.cg.shared.global [%0], [%1], 16;" :: "r"(dst), "l"(src));
}
#define CPA_COMMIT() asm volatile("cp.async.commit_group;")
#define CPA_WAIT0()  asm volatile("cp.async.wait_group 0;")

__device__ __forceinline__ unsigned int smem_u32(const void* p) {
    unsigned int a;
    asm("{ .reg .u64 t; cvta.to.shared.u64 t, %1; cvt.u32.u64 %0, t; }" : "=r"(a) : "l"(p));
    return a;
}

// hardware tanh (sm_75+): 1 MUFU op, max abs err ~1e-4
__device__ __forceinline__ float tanhapx(float x) {
    float y;
    asm("tanh.approx.f32 %0, %1;" : "=f"(y) : "f"(x));
    return y;
}

// Split grid barrier (single-counter, R11/R12-proven).
__device__ __forceinline__ void grid_arrive() {
    __threadfence();
    __syncthreads();
    if (threadIdx.x == 0) {
        if (atomicAdd(&g_count, 1u) == NCTA - 1u) {
            atomicExch(&g_count, 0u);
            __threadfence();
            atomicAdd(&g_gen, 1u);
        }
    }
}
__device__ __forceinline__ void grid_wait(unsigned int target) {
    if (threadIdx.x == 0) {
        volatile unsigned int* vg = &g_gen;
        while ((int)(*vg - target) < 0) {}
    }
    __syncthreads();
}

// GEMM segments: W + z from smem only (proven inner loop).
__device__ __forceinline__ void gemm_seg32(const float* wp, const float* zp,
                                           float& a0, float& a1, float& a2, float& a3) {
    #pragma unroll 8
    for (int j = 0; j < 32; ++j) {
        float4 w  = *(const float4*)(wp + (j << 6));
        float4 z0 = *(const float4*)(zp + (j << 2));
        float4 z1 = *(const float4*)(zp + 512  + (j << 2));
        float4 z2 = *(const float4*)(zp + 1024 + (j << 2));
        float4 z3 = *(const float4*)(zp + 1536 + (j << 2));
        a0 += z0.x*w.x; a0 += z0.y*w.y; a0 += z0.z*w.z; a0 += z0.w*w.w;
        a1 += z1.x*w.x; a1 += z1.y*w.y; a1 += z1.z*w.z; a1 += z1.w*w.w;
        a2 += z2.x*w.x; a2 += z2.y*w.y; a2 += z2.z*w.z; a2 += z2.w*w.w;
        a3 += z3.x*w.x; a3 += z3.y*w.y; a3 += z3.z*w.z; a3 += z3.w*w.w;
    }
}
__device__ __forceinline__ void gemm_seg64(const float* wp, const float* zp,
                                           float& a0, float& a1, float& a2, float& a3) {
    #pragma unroll 8
    for (int j = 0; j < 64; ++j) {
        float4 w  = *(const float4*)(wp + (j << 6));
        float4 z0 = *(const float4*)(zp + (j << 2));
        float4 z1 = *(const float4*)(zp + 512  + (j << 2));
        float4 z2 = *(const float4*)(zp + 1024 + (j << 2));
        float4 z3 = *(const float4*)(zp + 1536 + (j << 2));
        a0 += z0.x*w.x; a0 += z0.y*w.y; a0 += z0.z*w.z; a0 += z0.w*w.w;
        a1 += z1.x*w.x; a1 += z1.y*w.y; a1 += z1.z*w.z; a1 += z1.w*w.w;
        a2 += z2.x*w.x; a2 += z2.y*w.y; a2 += z2.z*w.z; a2 += z2.w*w.w;
        a3 += z3.x*w.x; a3 += z3.y*w.y; a3 += z3.z*w.z; a3 += z3.w*w.w;
    }
}

__global__ void __launch_bounds__(NTHR, 1)
lstm_persistent(const float* __restrict__ x,
                const void* __restrict__ length,
                const float* __restrict__ Wih0, const float* __restrict__ Whh0,
                const float* __restrict__ b0v,
                const float* __restrict__ Wih1, const float* __restrict__ Whh1,
                const float* __restrict__ b1v)
{
    extern __shared__ float smem[];
    float* buf0    = smem + BUF0_OFF;
    float* buf1    = smem + BUF1_OFF;
    float* W0_s    = smem + W0_OFF;
    float* wbufA   = smem + WBA_OFF;
    float* wbufB   = smem + WBB_OFF;
    float* gates_s = smem + G_OFF;
    int*   sidx_s  = (int*)(smem + SRT_OFF);
    int*   lenS_s  = (int*)(smem + SRT_OFF + 32);
    const unsigned int b0_u = smem_u32(buf0);
    const unsigned int b1_u = smem_u32(buf1);
    const unsigned int wA_u = smem_u32(wbufA);
    const unsigned int wB_u = smem_u32(wbufB);

    const int tid   = threadIdx.x;
    const int hbase = blockIdx.x * 4;

    const unsigned int bar_base = *((volatile unsigned int*)&g_gen);

    // ---- length sort (desc, idx-asc ties) -> sorted batch space ----
    if (tid == 0) {
        int li[32], si[32];
        #pragma unroll
        for (int i = 0; i < 32; ++i) { li[i] = load_length(length, i); si[i] = i; }
        for (int i = 0; i < 31; ++i) {
            int m = i;
            for (int j = i + 1; j < 32; ++j) if (li[j] > li[m]) m = j;
            int tl = li[i]; li[i] = li[m]; li[m] = tl;
            int ts = si[i]; si[i] = si[m]; si[m] = ts;
        }
        for (int i = 0; i < 32; ++i) {
            lenS_s[i] = li[i]; sidx_s[i] = si[i]; g_sidx_d[i] = si[i];
        }
    }
    __syncthreads();

    const int c   = tid & 15;              // gate column (c = hh*4 + gate)
    const int bh_ = (tid >> 4) & 1;
    const int wid = tid >> 5;
    const int kh  = wid & 1;               // K-half
    const int bgs = wid >> 1;
    const int bg  = bgs ^ (bgs >> 1);      // {0,1,3,2}: SMSP pairs {0,3},{1,2}
    const int b0i = bg*8 + bh_*4;          // 4 sorted batch rows per thread

    const int eb  = tid & 31;              // elementwise mapping (tid<128), sorted space
    const int ehh = tid >> 5;
    const int lb   = lenS_s[eb];           // per-batch freeze point (sorted)
    const int wmax = lenS_s[bg*8];         // warp-uniform max length of its octile

    // ---- pre-phase 1: W0 resident in smem ----
    for (int i = tid; i < 16384; i += NTHR) {
        int k  = i >> 4;
        int cc = i & 15;
        int col = ((cc & 3) << 9) + hbase + (cc >> 2);
        float w = (k < 512) ? Wih0[(size_t)k*2048 + col]
                            : Whh0[(size_t)(k-512)*2048 + col];
        W0_s[((k >> 2) << 6) + (cc << 2) + (k & 3)] = w;
    }

    // ---- pre-phase 2: W1 -> per-CTA gmem slice, phase-major layout ----
    {
        float* dst = g_W1t + (size_t)blockIdx.x * 16384;
        for (int i = tid; i < 16384; i += NTHR) {
            int p    = i >> 12;
            int khh  = (i >> 11) & 1;
            int j    = (i >> 6) & 31;
            int cc2  = i & 63;
            int cidx = cc2 >> 2;
            int klow = cc2 & 3;
            int k4g  = ((p & 1) << 5) + (khh << 6) + (((p >> 1) & 1) << 7) + j;
            int k    = (k4g << 2) + klow;
            int col  = ((cidx & 3) << 9) + hbase + (cidx >> 2);
            dst[i] = (k < 512) ? Wih1[(size_t)k*2048 + col]
                               : Whh1[(size_t)(k-512)*2048 + col];
        }
    }
    __threadfence();
    __syncthreads();

    const float* W1g = g_W1t + (size_t)blockIdx.x * 16384;
    const float bv0 = b0v[((c & 3) << 9) + hbase + (c >> 2)];
    const float bv1 = b1v[((c & 3) << 9) + hbase + (c >> 2)];

    // ---- prime: x(0) (permuted rows) -> buf0, W1 phase0 -> wbufA ----
    #pragma unroll
    for (int j = 0; j < 16; ++j) {
        int i = tid + j*NTHR;
        int b = i >> 7, k4 = i & 127;
        cpa16(b0_u + ((b << 9) + (k4 << 2))*4, x + sidx_s[b]*512 + (k4 << 2));
    }
    #pragma unroll
    for (int j = 0; j < 4; ++j) {
        int i = tid + j*NTHR;
        cpa16(wA_u + (i << 4), W1g + (i << 2));
    }
    CPA_COMMIT();

    float c0reg = 0.f, h0reg = 0.f;   // layer-0 state (tid<128)
    float c1reg = 0.f, h1reg = 0.f;   // layer-1 state

    for (int s = 0; s <= TT; ++s) {
        const bool doL0 = (s < TT);
        const bool doL1 = (s >= 1);
        const bool actL0 = (s < wmax);             // warp-uniform GEMM guards
        const bool actL1 = doL1 && (s - 1 < wmax);
        float* bx = (s & 1) ? buf1 : buf0;            // holds x(s)
        float* bz = (s & 1) ? buf0 : buf1;            // gets hA(s), then x(s+1)
        const unsigned int bx_u = (s & 1) ? b1_u : b0_u;
        const unsigned int bz_u = (s & 1) ? b0_u : b1_u;

        // T0: everything from previous superstep landed (x(s), W1 phase0)
        CPA_WAIT0();
        __syncthreads();

        float a0 = 0.f, a1 = 0.f, a2 = 0.f, a3 = 0.f;
        const float* zpx = bx + b0i*512 + kh*256;

        // L0 x-GEMM phase A
        if (actL0) gemm_seg32(W0_s + kh*4096 + (c << 2), zpx, a0, a1, a2, a3);

        // wait superstep s-1 complete (h rows for s ready)
        grid_wait(bar_base + (unsigned)s);

        // G1: hA(s) -> bz   (h buffers already in sorted space)
        {
            const float* hrow = g_hA + (size_t)s*ROWSZ;
            #pragma unroll
            for (int j = 0; j < 16; ++j) {
                int i = tid + j*NTHR;
                int b = i >> 7, k4 = i & 127;
                cpa16(bz_u + ((b << 9) + (k4 << 2))*4, hrow + b*512 + (k4 << 2));
            }
            CPA_COMMIT();
        }

        // L0 x-GEMM phase B — hides G1
        if (actL0) gemm_seg32(W0_s + kh*4096 + 2048 + (c << 2), zpx + 128, a0, a1, a2, a3);

        CPA_WAIT0();          // G1 done; bx(x) reads closed
        __syncthreads();

        // G2: hB(s-1) -> bx (x dead)  +  W1 phase1 -> wbufB
        {
            const float* hrowB = g_hB + (size_t)(doL1 ? s-1 : 0)*ROWSZ;
            #pragma unroll
            for (int j = 0; j < 16; ++j) {
                int i = tid + j*NTHR;
                int b = i >> 7, k4 = i & 127;
                cpa16(bx_u + ((b << 9) + (k4 << 2))*4, hrowB + b*512 + (k4 << 2));
            }
            #pragma unroll
            for (int j = 0; j < 4; ++j) {
                int i = tid + j*NTHR;
                cpa16(wB_u + (i << 4), W1g + 4096 + (i << 2));
            }
            CPA_COMMIT();
        }

        // L0 h-GEMM from bz=hA(s) — hides G2
        if (actL0) {
            gemm_seg64(W0_s + 8192 + kh*4096 + (c << 2),
                       bz + b0i*512 + kh*256, a0, a1, a2, a3);
        }

        // L0 reduce + elementwise (syncs unconditional; frozen-batch slots stale-safe)
        if (doL0 && kh == 1) {
            gates_s[(b0i+0)*17 + c] = a0;
            gates_s[(b0i+1)*17 + c] = a1;
            gates_s[(b0i+2)*17 + c] = a2;
            gates_s[(b0i+3)*17 + c] = a3;
        }
        __syncthreads();
        if (doL0 && kh == 0) {
            gates_s[(b0i+0)*17 + c] += a0 + bv0;
            gates_s[(b0i+1)*17 + c] += a1 + bv0;
            gates_s[(b0i+2)*17 + c] += a2 + bv0;
            gates_s[(b0i+3)*17 + c] += a3 + bv0;
        }
        __syncthreads();
        if (doL0 && tid < 128) {
            float fg = gates_s[eb*17 + ehh*4 + 0];
            float ig = gates_s[eb*17 + ehh*4 + 1];
            float og = gates_s[eb*17 + ehh*4 + 2];
            float gg = gates_s[eb*17 + ehh*4 + 3];
            float cn, hn;
            if (s < lb) {
                float sf = 0.5f*tanhapx(0.5f*fg) + 0.5f;
                float si = 0.5f*tanhapx(0.5f*ig) + 0.5f;
                float so = 0.5f*tanhapx(0.5f*og) + 0.5f;
                cn = sf*c0reg + si*tanhapx(gg);
                hn = so*tanhapx(cn);
            } else { cn = c0reg; hn = h0reg; }
            c0reg = cn; h0reg = hn;
            g_hA[(size_t)(s+1)*ROWSZ + eb*512 + hbase + ehh] = hn;
        }

        // ---- layer 1 (timestep s-1) ----
        float d0 = 0.f, d1 = 0.f, d2 = 0.f, d3 = 0.f;
        const float* zpa = bz + b0i*512 + kh*256;   // hA(s)
        const float* zpb = bx + b0i*512 + kh*256;   // hB(s-1)

        // L1 x-GEMM phase A from wbufA(phase0)
        if (actL1) gemm_seg32(wbufA + kh*2048 + (c << 2), zpa, d0, d1, d2, d3);

        CPA_WAIT0();          // G2 done (bx=hB, wbufB=phase1)
        __syncthreads();

        // G3: W1 phase2 -> wbufA
        #pragma unroll
        for (int j = 0; j < 4; ++j) {
            int i = tid + j*NTHR;
            cpa16(wA_u + (i << 4), W1g + 8192 + (i << 2));
        }
        CPA_COMMIT();

        // L1 x-GEMM phase B from wbufB(phase1) — hides G3
        if (actL1) gemm_seg32(wbufB + kh*2048 + (c << 2), zpa + 128, d0, d1, d2, d3);

        CPA_WAIT0();          // G3 done
        __syncthreads();

        // G4: W1 phase3 -> wbufB  +  x(s+1) (permuted rows) -> bz
        {
            int tn = (s + 1 < TT) ? (s + 1) : (TT - 1);
            const float* xnext = x + (size_t)tn*ROWSZ;
            #pragma unroll
            for (int j = 0; j < 4; ++j) {
                int i = tid + j*NTHR;
                cpa16(wB_u + (i << 4), W1g + 12288 + (i << 2));
            }
            #pragma unroll
            for (int j = 0; j < 16; ++j) {
                int i = tid + j*NTHR;
                int b = i >> 7, k4 = i & 127;
                cpa16(bz_u + ((b << 9) + (k4 << 2))*4, xnext + sidx_s[b]*512 + (k4 << 2));
            }
            CPA_COMMIT();
        }

        // L1 h-GEMM phase A from wbufA(phase2) — hides G4
        if (actL1) gemm_seg32(wbufA + kh*2048 + (c << 2), zpb, d0, d1, d2, d3);

        CPA_WAIT0();          // G4 done
        __syncthreads();

        // G5: W1 phase0 -> wbufA for next superstep
        #pragma unroll
        for (int j = 0; j < 4; ++j) {
            int i = tid + j*NTHR;
            cpa16(wA_u + (i << 4), W1g + (i << 2));
        }
        CPA_COMMIT();

        // L1 h-GEMM phase B from wbufB(phase3) — hides G5
        if (actL1) gemm_seg32(wbufB + kh*2048 + (c << 2), zpb + 128, d0, d1, d2, d3);

        // L1 reduce + elementwise
        if (doL1 && kh == 1) {
            gates_s[(b0i+0)*17 + c] = d0;
            gates_s[(b0i+1)*17 + c] = d1;
            gates_s[(b0i+2)*17 + c] = d2;
            gates_s[(b0i+3)*17 + c] = d3;
        }
        __syncthreads();
        if (doL1 && kh == 0) {
            gates_s[(b0i+0)*17 + c] += d0 + bv1;
            gates_s[(b0i+1)*17 + c] += d1 + bv1;
            gates_s[(b0i+2)*17 + c] += d2 + bv1;
            gates_s[(b0i+3)*17 + c] += d3 + bv1;
        }
        __syncthreads();
        if (doL1 && tid < 128) {
            float fg = gates_s[eb*17 + ehh*4 + 0];
            float ig = gates_s[eb*17 + ehh*4 + 1];
            float og = gates_s[eb*17 + ehh*4 + 2];
            float gg = gates_s[eb*17 + ehh*4 + 3];
            float cn, hn;
            if ((s - 1) < lb) {
                float sf = 0.5f*tanhapx(0.5f*fg) + 0.5f;
                float si = 0.5f*tanhapx(0.5f*ig) + 0.5f;
                float so = 0.5f*tanhapx(0.5f*og) + 0.5f;
                cn = sf*c1reg + si*tanhapx(gg);
                hn = so*tanhapx(cn);
            } else { cn = c1reg; hn = h1reg; }
            c1reg = cn; h1reg = hn;
            g_hB[(size_t)s*ROWSZ + eb*512 + hbase + ehh] = hn;
        }

        grid_arrive();   // gen -> bar_base + s + 1
    }
}

// out[(t*B + sidx[j])*64 + a] = hB_sorted[j] . Wfc[:,a] + bfc[a]
__global__ void __launch_bounds__(256)
fc_kernel(const float* __restrict__ Wfc, const float* __restrict__ bfc,
          float* __restrict__ out)
{
    __shared__ float w_s[128*64];
    __shared__ float h_s[32*128];
    const int tid = threadIdx.x;
    const int rbase = blockIdx.x * 32;
    const int a  = tid & 63;
    const int r4 = tid >> 6;

    float acc[8];
    float bvv = bfc[a];
    #pragma unroll
    for (int j = 0; j < 8; ++j) acc[j] = bvv;

    for (int kc = 0; kc < 512; kc += 128) {
        __syncthreads();
        for (int i = tid; i < 128*64/4; i += 256)
            ((float4*)w_s)[i] = ((const float4*)(Wfc + (size_t)kc*64))[i];
        for (int i = tid; i < 32*128/4; i += 256) {
            int r  = i >> 5;
            int k4 = i & 31;
            ((float4*)(h_s + r*128))[k4] =
                *(const float4*)(g_hB + (size_t)(rbase + r + BB)*512 + kc + (k4 << 2));
        }
        __syncthreads();
        #pragma unroll 4
        for (int k = 0; k < 128; ++k) {
            float w = w_s[(k << 6) + a];
            #pragma unroll
            for (int j = 0; j < 8; ++j)
                acc[j] += h_s[(r4 + 4*j)*128 + k] * w;
        }
    }
    #pragma unroll
    for (int j = 0; j < 8; ++j) {
        int slot = r4 + 4*j;                       // sorted batch slot
        out[((size_t)rbase + g_sidx_d[slot])*64 + a] = acc[j];
    }
}

extern "C" void kernel_launch(void* const* d_in, const int* in_sizes, int n_in,
                              void* d_out, int out_size)
{
    const float* x      = (const float*)d_in[0];
    const void*  length = (const void*)d_in[1];
    const float* Wih0   = (const float*)d_in[2];
    const float* Whh0   = (const float*)d_in[3];
    const float* b0v    = (const float*)d_in[4];
    const float* Wih1   = (const float*)d_in[5];
    const float* Whh1   = (const float*)d_in[6];
    const float* b1v    = (const float*)d_in[7];
    const float* Wfc    = (const float*)d_in[8];
    const float* bfc    = (const float*)d_in[9];
    float* out = (float*)d_out;

    const int smem_bytes = SMEM_FLOATS * (int)sizeof(float); // ~226.4 KB
    cudaFuncSetAttribute(lstm_persistent,
                         cudaFuncAttributeMaxDynamicSharedMemorySize, smem_bytes);

    lstm_persistent<<<NCTA, NTHR, smem_bytes>>>(x, length, Wih0, Whh0, b0v,
                                                Wih1, Whh1, b1v);
    fc_kernel<<<(TT*BB)/32, 256>>>(Wfc, bfc, out);
}

// round 17
// speedup vs baseline: 1.4651x; 1.0106x over previous
#include <cuda_runtime.h>

#define TT    2048
#define BB    32
#define NCTA  128
#define NTHR  256
#define ROWSZ (BB*512)        // 16384 floats per timestep of h

// smem layout (floats)
#define BUF0_OFF 0            // role-swapping z buffer 0: [32][512]
#define BUF1_OFF 16384        // role-swapping z buffer 1: [32][512]
#define W0_OFF   32768        // W0 resident: 16384
#define WBA_OFF  49152        // W1 stream buf A: 4096
#define WBB_OFF  53248        // W1 stream buf B: 4096
#define G_OFF    57344        // L0 gates: 32*17 (L1 gates alias into dead bx)
#define SRT_OFF  (G_OFF + 32*17)      // sidx[32] + lenS[32] + masks[2]
#define SMEM_FLOATS (SRT_OFF + 66)    // 57954 floats ~ 226.4 KB

__device__ __align__(256) float g_hA[(TT+1)*ROWSZ];
__device__ __align__(256) float g_hB[(TT+1)*ROWSZ];
__device__ __align__(256) float g_W1t[NCTA*16384];    // 8 MB phase-major W1
__device__ int g_sidx_d[32];
__device__ unsigned int g_count = 0;
__device__ unsigned int g_gen   = 0;

// JAX silently downcasts int64->int32 unless x64 mode is on; detect at runtime.
__device__ __forceinline__ int load_length(const void* lp, int b) {
    const int* L = (const int*)lp;
    bool is64 = true;
    #pragma unroll
    for (int w = 1; w < 32; w += 2) is64 &= (L[w] == 0);
    return is64 ? (int)((const long long*)lp)[b] : L[b];
}

__device__ __forceinline__ void cpa16(unsigned int dst, const void* src) {
    asm volatile("cp.async.cg.shared.global [%0], [%1], 16;" :: "r"(dst), "l"(src));
}
#define CPA_COMMIT() asm volatile("cp.async.commit_group;")
#define CPA_WAIT0()  asm volatile("cp.async.wait_group 0;")

__device__ __forceinline__ unsigned int smem_u32(const void* p) {
    unsigned int a;
    asm("{ .reg .u64 t; cvta.to.shared.u64 t, %1; cvt.u32.u64 %0, t; }" : "=r"(a) : "l"(p));
    return a;
}

// hardware tanh (sm_75+): 1 MUFU op, max abs err ~1e-4
__device__ __forceinline__ float tanhapx(float x) {
    float y;
    asm("tanh.approx.f32 %0, %1;" : "=f"(y) : "f"(x));
    return y;
}

// Split grid barrier (single-counter, R11/R12-proven).
__device__ __forceinline__ void grid_arrive() {
    __threadfence();
    __syncthreads();
    if (threadIdx.x == 0) {
        if (atomicAdd(&g_count, 1u) == NCTA - 1u) {
            atomicExch(&g_count, 0u);
            __threadfence();
            atomicAdd(&g_gen, 1u);
        }
    }
}
__device__ __forceinline__ void grid_wait(unsigned int target) {
    if (threadIdx.x == 0) {
        volatile unsigned int* vg = &g_gen;
        while ((int)(*vg - target) < 0) {}
    }
    __syncthreads();
}

// GEMM segments: W + z from smem only (proven inner loop).
__device__ __forceinline__ void gemm_seg32(const float* wp, const float* zp,
                                           float& a0, float& a1, float& a2, float& a3) {
    #pragma unroll 8
    for (int j = 0; j < 32; ++j) {
        float4 w  = *(const float4*)(wp + (j << 6));
        float4 z0 = *(const float4*)(zp + (j << 2));
        float4 z1 = *(const float4*)(zp + 512  + (j << 2));
        float4 z2 = *(const float4*)(zp + 1024 + (j << 2));
        float4 z3 = *(const float4*)(zp + 1536 + (j << 2));
        a0 += z0.x*w.x; a0 += z0.y*w.y; a0 += z0.z*w.z; a0 += z0.w*w.w;
        a1 += z1.x*w.x; a1 += z1.y*w.y; a1 += z1.z*w.z; a1 += z1.w*w.w;
        a2 += z2.x*w.x; a2 += z2.y*w.y; a2 += z2.z*w.z; a2 += z2.w*w.w;
        a3 += z3.x*w.x; a3 += z3.y*w.y; a3 += z3.z*w.z; a3 += z3.w*w.w;
    }
}
__device__ __forceinline__ void gemm_seg64(const float* wp, const float* zp,
                                           float& a0, float& a1, float& a2, float& a3) {
    #pragma unroll 8
    for (int j = 0; j < 64; ++j) {
        float4 w  = *(const float4*)(wp + (j << 6));
        float4 z0 = *(const float4*)(zp + (j << 2));
        float4 z1 = *(const float4*)(zp + 512  + (j << 2));
        float4 z2 = *(const float4*)(zp + 1024 + (j << 2));
        float4 z3 = *(const float4*)(zp + 1536 + (j << 2));
        a0 += z0.x*w.x; a0 += z0.y*w.y; a0 += z0.z*w.z; a0 += z0.w*w.w;
        a1 += z1.x*w.x; a1 += z1.y*w.y; a1 += z1.z*w.z; a1 += z1.w*w.w;
        a2 += z2.x*w.x; a2 += z2.y*w.y; a2 += z2.z*w.z; a2 += z2.w*w.w;
        a3 += z3.x*w.x; a3 += z3.y*w.y; a3 += z3.z*w.z; a3 += z3.w*w.w;
    }
}

__global__ void __launch_bounds__(NTHR, 1)
lstm_persistent(const float* __restrict__ x,
                const void* __restrict__ length,
                const float* __restrict__ Wih0, const float* __restrict__ Whh0,
                const float* __restrict__ b0v,
                const float* __restrict__ Wih1, const float* __restrict__ Whh1,
                const float* __restrict__ b1v)
{
    extern __shared__ float smem[];
    float* buf0    = smem + BUF0_OFF;
    float* buf1    = smem + BUF1_OFF;
    float* W0_s    = smem + W0_OFF;
    float* wbufA   = smem + WBA_OFF;
    float* wbufB   = smem + WBB_OFF;
    float* gates_s = smem + G_OFF;
    int*   sidx_s  = (int*)(smem + SRT_OFF);
    int*   lenS_s  = (int*)(smem + SRT_OFF + 32);
    int*   msk_s   = (int*)(smem + SRT_OFF + 64);
    const unsigned int b0_u = smem_u32(buf0);
    const unsigned int b1_u = smem_u32(buf1);
    const unsigned int wA_u = smem_u32(wbufA);
    const unsigned int wB_u = smem_u32(wbufB);

    const int tid   = threadIdx.x;
    const int hbase = blockIdx.x * 4;

    const unsigned int bar_base = *((volatile unsigned int*)&g_gen);

    // ---- length sort (desc, idx-asc ties) -> sorted batch space ----
    if (tid == 0) {
        int li[32], si[32];
        #pragma unroll
        for (int i = 0; i < 32; ++i) { li[i] = load_length(length, i); si[i] = i; }
        for (int i = 0; i < 31; ++i) {
            int m = i;
            for (int j = i + 1; j < 32; ++j) if (li[j] > li[m]) m = j;
            int tl = li[i]; li[i] = li[m]; li[m] = tl;
            int ts = si[i]; si[i] = si[m]; si[m] = ts;
        }
        for (int i = 0; i < 32; ++i) {
            lenS_s[i] = li[i]; sidx_s[i] = si[i]; g_sidx_d[i] = si[i];
        }
    }
    __syncthreads();

    const int c   = tid & 15;              // gate column (c = hh*4 + gate)
    const int bh_ = (tid >> 4) & 1;
    const int wid = tid >> 5;
    const int kh  = wid & 1;               // K-half
    const int bgs = wid >> 1;
    const int bg  = bgs ^ (bgs >> 1);      // {0,1,3,2}: SMSP pairs {0,3},{1,2}
    const int b0i = bg*8 + bh_*4;          // 4 sorted batch rows per thread

    const int eb  = tid & 31;              // elementwise mapping (tid<128), sorted space
    const int ehh = tid >> 5;
    const int lb   = lenS_s[eb];           // per-batch freeze point (sorted)
    const int wmax = lenS_s[bg*8];         // warp-uniform max length of its octile

    // ---- pre-phase 1: W0 resident in smem ----
    for (int i = tid; i < 16384; i += NTHR) {
        int k  = i >> 4;
        int cc = i & 15;
        int col = ((cc & 3) << 9) + hbase + (cc >> 2);
        float w = (k < 512) ? Wih0[(size_t)k*2048 + col]
                            : Whh0[(size_t)(k-512)*2048 + col];
        W0_s[((k >> 2) << 6) + (cc << 2) + (k & 3)] = w;
    }

    // ---- pre-phase 2: W1 -> per-CTA gmem slice, phase-major layout ----
    {
        float* dst = g_W1t + (size_t)blockIdx.x * 16384;
        for (int i = tid; i < 16384; i += NTHR) {
            int p    = i >> 12;
            int khh  = (i >> 11) & 1;
            int j    = (i >> 6) & 31;
            int cc2  = i & 63;
            int cidx = cc2 >> 2;
            int klow = cc2 & 3;
            int k4g  = ((p & 1) << 5) + (khh << 6) + (((p >> 1) & 1) << 7) + j;
            int k    = (k4g << 2) + klow;
            int col  = ((cidx & 3) << 9) + hbase + (cidx >> 2);
            dst[i] = (k < 512) ? Wih1[(size_t)k*2048 + col]
                               : Whh1[(size_t)(k-512)*2048 + col];
        }
    }
    __threadfence();
    __syncthreads();

    const float* W1g = g_W1t + (size_t)blockIdx.x * 16384;
    const float bv0 = b0v[((c & 3) << 9) + hbase + (c >> 2)];
    const float bv1 = b1v[((c & 3) << 9) + hbase + (c >> 2)];

    // ---- prime: x(0) (permuted, active rows) -> buf0, W1 phase0 -> wbufA ----
    #pragma unroll
    for (int j = 0; j < 16; ++j) {
        int i = tid + j*NTHR;
        int b = i >> 7, k4 = i & 127;
        if (lenS_s[b] > 0)
            cpa16(b0_u + ((b << 9) + (k4 << 2))*4, x + sidx_s[b]*512 + (k4 << 2));
    }
    #pragma unroll
    for (int j = 0; j < 4; ++j) {
        int i = tid + j*NTHR;
        cpa16(wA_u + (i << 4), W1g + (i << 2));
    }
    CPA_COMMIT();

    float c0reg = 0.f;                // layer-0 cell state (tid<128)
    float c1reg = 0.f, h1reg = 0.f;   // layer-1 state

    for (int s = 0; s <= TT; ++s) {
        const bool doL0 = (s < TT);
        const bool doL1 = (s >= 1);
        const bool actL0 = (s < wmax);             // warp-uniform GEMM guards
        const bool actL1 = doL1 && (s - 1 < wmax);
        float* bx = (s & 1) ? buf1 : buf0;            // holds x(s); later hB(s-1); gates alias
        float* bz = (s & 1) ? buf0 : buf1;            // gets hA(s), then x(s+1)
        const unsigned int bx_u = (s & 1) ? b1_u : b0_u;
        const unsigned int bz_u = (s & 1) ? b0_u : b1_u;

        // T0: everything from previous superstep landed (x(s), W1 phase0)
        CPA_WAIT0();
        if (wid == 0) {
            unsigned m1 = __ballot_sync(0xffffffffu, s <= lenS_s[tid]);      // h rows needed
            unsigned m2 = __ballot_sync(0xffffffffu, (s + 1) < lenS_s[tid]); // x(s+1) needed
            if (tid == 0) { msk_s[0] = (int)m1; msk_s[1] = (int)m2; }
        }
        __syncthreads();
        const int mh = msk_s[0];
        const int mx = msk_s[1];

        float a0 = 0.f, a1 = 0.f, a2 = 0.f, a3 = 0.f;
        float d0 = 0.f, d1 = 0.f, d2 = 0.f, d3 = 0.f;
        const float* zpx = bx + b0i*512 + kh*256;

        // L0 x-GEMM phase A — absorbs barrier skew
        if (actL0) gemm_seg32(W0_s + kh*4096 + (c << 2), zpx, a0, a1, a2, a3);

        // wait superstep s-1 complete (h rows for s ready)
        grid_wait(bar_base + (unsigned)s);

        // G1: hA(s) -> bz (active batches only)
        {
            const float* hrow = g_hA + (size_t)s*ROWSZ;
            #pragma unroll
            for (int j = 0; j < 16; ++j) {
                int i = tid + j*NTHR;
                int b = i >> 7, k4 = i & 127;
                if ((mh >> b) & 1)
                    cpa16(bz_u + ((b << 9) + (k4 << 2))*4, hrow + b*512 + (k4 << 2));
            }
            CPA_COMMIT();
        }

        // L0 x-GEMM phase B — hides G1
        if (actL0) gemm_seg32(W0_s + kh*4096 + 2048 + (c << 2), zpx + 128, a0, a1, a2, a3);

        CPA_WAIT0();          // G1 done; bx(x) reads closed
        __syncthreads();

        // G2: hB(s-1) -> bx (x dead, active batches)  +  W1 phase1 -> wbufB
        {
            const float* hrowB = g_hB + (size_t)(doL1 ? s-1 : 0)*ROWSZ;
            #pragma unroll
            for (int j = 0; j < 16; ++j) {
                int i = tid + j*NTHR;
                int b = i >> 7, k4 = i & 127;
                if ((mh >> b) & 1)
                    cpa16(bx_u + ((b << 9) + (k4 << 2))*4, hrowB + b*512 + (k4 << 2));
            }
            #pragma unroll
            for (int j = 0; j < 4; ++j) {
                int i = tid + j*NTHR;
                cpa16(wB_u + (i << 4), W1g + 4096 + (i << 2));
            }
            CPA_COMMIT();
        }

        // L0 h-GEMM (bz=hA) + L1 x-GEMM phase A (wbufA=phase0, bz=hA) — hide G2
        if (actL0) gemm_seg64(W0_s + 8192 + kh*4096 + (c << 2),
                              bz + b0i*512 + kh*256, a0, a1, a2, a3);
        const float* zpa = bz + b0i*512 + kh*256;   // hA(s)
        if (actL1) gemm_seg32(wbufA + kh*2048 + (c << 2), zpa, d0, d1, d2, d3);

        CPA_WAIT0();          // G2 done (bx=hB, wbufB=phase1)
        __syncthreads();

        // G3: W1 phase2 -> wbufA (phase0 consumed)
        #pragma unroll
        for (int j = 0; j < 4; ++j) {
            int i = tid + j*NTHR;
            cpa16(wA_u + (i << 4), W1g + 8192 + (i << 2));
        }
        CPA_COMMIT();

        // L1 x-GEMM phase B (wbufB=phase1) — hides G3
        if (actL1) gemm_seg32(wbufB + kh*2048 + (c << 2), zpa + 128, d0, d1, d2, d3);

        CPA_WAIT0();          // G3 done
        __syncthreads();

        // G4: W1 phase3 -> wbufB  +  x(s+1) -> bz (hA reads closed; active rows)
        {
            int tn = (s + 1 < TT) ? (s + 1) : (TT - 1);
            const float* xnext = x + (size_t)tn*ROWSZ;
            #pragma unroll
            for (int j = 0; j < 4; ++j) {
                int i = tid + j*NTHR;
                cpa16(wB_u + (i << 4), W1g + 12288 + (i << 2));
            }
            #pragma unroll
            for (int j = 0; j < 16; ++j) {
                int i = tid + j*NTHR;
                int b = i >> 7, k4 = i & 127;
                if ((mx >> b) & 1)
                    cpa16(bz_u + ((b << 9) + (k4 << 2))*4, xnext + sidx_s[b]*512 + (k4 << 2));
            }
            CPA_COMMIT();
        }

        // L1 h-GEMM phase A (wbufA=phase2, bx=hB) — hides G4
        const float* zpb = bx + b0i*512 + kh*256;   // hB(s-1)
        if (actL1) gemm_seg32(wbufA + kh*2048 + (c << 2), zpb, d0, d1, d2, d3);

        CPA_WAIT0();          // G4 done
        __syncthreads();

        // G5: W1 phase0 -> wbufA for next superstep
        #pragma unroll
        for (int j = 0; j < 4; ++j) {
            int i = tid + j*NTHR;
            cpa16(wA_u + (i << 4), W1g + (i << 2));
        }
        CPA_COMMIT();

        // L1 h-GEMM phase B (wbufB=phase3) — hides G5
        if (actL1) gemm_seg32(wbufB + kh*2048 + (c << 2), zpb + 128, d0, d1, d2, d3);

        // ---- merged reduce: L0 -> gates_s, L1 -> bx alias (dead until next G1) ----
        __syncthreads();      // R1: all GEMM reads of bx/bz/wbufs closed
        float* bxal = bx;     // first 544 floats of bx as L1 gate scratch
        if (kh == 1) {
            gates_s[(b0i+0)*17 + c] = a0;
            gates_s[(b0i+1)*17 + c] = a1;
            gates_s[(b0i+2)*17 + c] = a2;
            gates_s[(b0i+3)*17 + c] = a3;
            bxal[(b0i+0)*17 + c] = d0;
            bxal[(b0i+1)*17 + c] = d1;
            bxal[(b0i+2)*17 + c] = d2;
            bxal[(b0i+3)*17 + c] = d3;
        }
        __syncthreads();      // R2
        if (kh == 0) {
            gates_s[(b0i+0)*17 + c] += a0 + bv0;
            gates_s[(b0i+1)*17 + c] += a1 + bv0;
            gates_s[(b0i+2)*17 + c] += a2 + bv0;
            gates_s[(b0i+3)*17 + c] += a3 + bv0;
            bxal[(b0i+0)*17 + c] += d0 + bv1;
            bxal[(b0i+1)*17 + c] += d1 + bv1;
            bxal[(b0i+2)*17 + c] += d2 + bv1;
            bxal[(b0i+3)*17 + c] += d3 + bv1;
        }
        __syncthreads();      // R3

        // ---- merged elementwise: both layers (tid<128) ----
        if (tid < 128) {
            if (doL0 && s < lb) {
                float fg = gates_s[eb*17 + ehh*4 + 0];
                float ig = gates_s[eb*17 + ehh*4 + 1];
                float og = gates_s[eb*17 + ehh*4 + 2];
                float gg = gates_s[eb*17 + ehh*4 + 3];
                float sf = 0.5f*tanhapx(0.5f*fg) + 0.5f;
                float si = 0.5f*tanhapx(0.5f*ig) + 0.5f;
                float so = 0.5f*tanhapx(0.5f*og) + 0.5f;
                float cn = sf*c0reg + si*tanhapx(gg);
                float hn = so*tanhapx(cn);
                c0reg = cn;
                g_hA[(size_t)(s+1)*ROWSZ + eb*512 + hbase + ehh] = hn;
            }
            if (doL1) {
                if (s - 1 < lb) {
                    float fg = bxal[eb*17 + ehh*4 + 0];
                    float ig = bxal[eb*17 + ehh*4 + 1];
                    float og = bxal[eb*17 + ehh*4 + 2];
                    float gg = bxal[eb*17 + ehh*4 + 3];
                    float sf = 0.5f*tanhapx(0.5f*fg) + 0.5f;
                    float si = 0.5f*tanhapx(0.5f*ig) + 0.5f;
                    float so = 0.5f*tanhapx(0.5f*og) + 0.5f;
                    float cn = sf*c1reg + si*tanhapx(gg);
                    float hn = so*tanhapx(cn);
                    c1reg = cn; h1reg = hn;
                }
                g_hB[(size_t)s*ROWSZ + eb*512 + hbase + ehh] = h1reg;
            }
        }

        grid_arrive();   // gen -> bar_base + s + 1
    }
}

// out[(t*B + sidx[j])*64 + a] = hB_sorted[j] . Wfc[:,a] + bfc[a]
__global__ void __launch_bounds__(256)
fc_kernel(const float* __restrict__ Wfc, const float* __restrict__ bfc,
          float* __restrict__ out)
{
    __shared__ float w_s[128*64];
    __shared__ float h_s[32*128];
    const int tid = threadIdx.x;
    const int rbase = blockIdx.x * 32;
    const int a  = tid & 63;
    const int r4 = tid >> 6;

    float acc[8];
    float bvv = bfc[a];
    #pragma unroll
    for (int j = 0; j < 8; ++j) acc[j] = bvv;

    for (int kc = 0; kc < 512; kc += 128) {
        __syncthreads();
        for (int i = tid; i < 128*64/4; i += 256)
            ((float4*)w_s)[i] = ((const float4*)(Wfc + (size_t)kc*64))[i];
        for (int i = tid; i < 32*128/4; i += 256) {
            int r  = i >> 5;
            int k4 = i & 31;
            ((float4*)(h_s + r*128))[k4] =
                *(const float4*)(g_hB + (size_t)(rbase + r + BB)*512 + kc + (k4 << 2));
        }
        __syncthreads();
        #pragma unroll 4
        for (int k = 0; k < 128; ++k) {
            float w = w_s[(k << 6) + a];
            #pragma unroll
            for (int j = 0; j < 8; ++j)
                acc[j] += h_s[(r4 + 4*j)*128 + k] * w;
        }
    }
    #pragma unroll
    for (int j = 0; j < 8; ++j) {
        int slot = r4 + 4*j;                       // sorted batch slot
        out[((size_t)rbase + g_sidx_d[slot])*64 + a] = acc[j];
    }
}

extern "C" void kernel_launch(void* const* d_in, const int* in_sizes, int n_in,
                              void* d_out, int out_size)
{
    const float* x      = (const float*)d_in[0];
    const void*  length = (const void*)d_in[1];
    const float* Wih0   = (const float*)d_in[2];
    const float* Whh0   = (const float*)d_in[3];
    const float* b0v    = (const float*)d_in[4];
    const float* Wih1   = (const float*)d_in[5];
    const float* Whh1   = (const float*)d_in[6];
    const float* b1v    = (const float*)d_in[7];
    const float* Wfc    = (const float*)d_in[8];
    const float* bfc    = (const float*)d_in[9];
    float* out = (float*)d_out;

    const int smem_bytes = SMEM_FLOATS * (int)sizeof(float); // ~226.4 KB
    cudaFuncSetAttribute(lstm_persistent,
                         cudaFuncAttributeMaxDynamicSharedMemorySize, smem_bytes);

    lstm_persistent<<<NCTA, NTHR, smem_bytes>>>(x, length, Wih0, Whh0, b0v,
                                                Wih1, Whh1, b1v);
    fc_kernel<<<(TT*BB)/32, 256>>>(Wfc, bfc, out);
}